// round 1
// baseline (speedup 1.0000x reference)
#include <cuda_runtime.h>
#include <math.h>

#define DMODEL 1024
#define DINNER 2048
#define DSTATE 16
#define SEQLEN 2048
#define NTOK   4096   /* BATCH * SEQLEN */

// ---------------- scratch (device globals; no runtime allocation) ----------------
__device__ float g_s [NTOK * DINNER];        // silu(z)
__device__ float g_u [NTOK * DINNER];        // conv output
__device__ float g_dt[NTOK * DINNER];        // clipped sigmoid dt
__device__ float g_y [NTOK * DINNER];        // scan output * silu(z)
__device__ float g_P [4 * DINNER * DINNER];  // conv_w repacked per-tap
__device__ float g_M [4 * DINNER * DMODEL];  // folded conv weights M_k = W_k @ Wxc
__device__ float g_Bm[NTOK * DSTATE];
__device__ float g_Cm[NTOK * DSTATE];

// ---------------- pack conv_w [d,i,4] -> 4 contiguous [d,i] matrices ----------------
__global__ void pack_conv(const float* __restrict__ cw) {
    int idx = blockIdx.x * 256 + threadIdx.x;          // 0 .. 2048*2048-1
    float4 v = reinterpret_cast<const float4*>(cw)[idx];
    g_P[0 * 4194304 + idx] = v.x;
    g_P[1 * 4194304 + idx] = v.y;
    g_P[2 * 4194304 + idx] = v.z;
    g_P[3 * 4194304 + idx] = v.w;
}

// ---------------- generic tiled fp32 GEMM ----------------
// MODE 0: C = A[M,K] @ W[N,K]^T          (activation x weight-row-major)
// MODE 1: conv-fold: A = x with 4-tap shifted K (K=4096 logical), W = g_M packed
// MODE 2: C = A[M,K] @ B[K,N]            (used for M_k precompute)
// EPI 0: none   EPI 1: silu   EPI 2: sigmoid + clip[1e-4,1]
template<int MODE, int EPI, bool HASB>
__global__ __launch_bounds__(256)
void gemm_k(const float* __restrict__ A, const float* __restrict__ W,
            const float* __restrict__ bias, float* __restrict__ out,
            int M, int N, int K)
{
    __shared__ float As[16][132];   // [k][m], padded
    __shared__ float Ws[16][68];    // [k][n], padded

    const int tid  = threadIdx.x;
    const int m0   = blockIdx.y * 128;
    const int n0   = blockIdx.x * 64;

    // global->reg tile load mappings
    const int a_row = tid >> 2;            // 0..63 (also row+64)
    const int a_col = (tid & 3) << 2;      // 0,4,8,12
    const int w_row = tid >> 2;            // MODE 0/1: 0..63
    const int w_col = (tid & 3) << 2;
    const int w_kr  = tid >> 4;            // MODE 2: 0..15
    const int w_nc  = (tid & 15) << 2;     // MODE 2: 0..60

    // compute mapping: warp tile 64(m) x 16(n); lane tile 8x4
    const int warp = tid >> 5, lane = tid & 31;
    const int wm = warp & 1, wn = warp >> 1;
    const int lm = lane >> 2, ln = lane & 3;
    const int cm = wm * 64 + lm * 4;
    const int cn = wn * 16 + ln * 4;

    float4 ar0, ar1, wr;
    float acc[8][4];
#pragma unroll
    for (int i = 0; i < 8; i++)
#pragma unroll
        for (int j = 0; j < 4; j++) acc[i][j] = 0.f;

    auto loadT = [&](int kt) {
        const int kb = kt * 16;
        if (MODE == 1) {
            // A: shifted x taps. kk in [0,4096): tap = kk>>10, j = kk&1023
            int kk = kb + a_col;
            int tap = kk >> 10, j = kk & 1023;
            int off = tap - 3;
            int r0 = m0 + a_row;
            ar0 = ((r0 & (SEQLEN - 1)) + off >= 0)
                ? *reinterpret_cast<const float4*>(A + (size_t)(r0 + off) * DMODEL + j)
                : make_float4(0.f, 0.f, 0.f, 0.f);
            int r1 = r0 + 64;
            ar1 = ((r1 & (SEQLEN - 1)) + off >= 0)
                ? *reinterpret_cast<const float4*>(A + (size_t)(r1 + off) * DMODEL + j)
                : make_float4(0.f, 0.f, 0.f, 0.f);
            // W: g_M[tap][d][j]
            int kk2 = kb + w_col;
            int tap2 = kk2 >> 10, j2 = kk2 & 1023;
            int d = n0 + w_row;
            wr = *reinterpret_cast<const float4*>(W + ((size_t)tap2 * DINNER + d) * DMODEL + j2);
        } else {
            ar0 = *reinterpret_cast<const float4*>(A + (size_t)(m0 + a_row) * K + kb + a_col);
            ar1 = *reinterpret_cast<const float4*>(A + (size_t)(m0 + a_row + 64) * K + kb + a_col);
            if (MODE == 0)
                wr = *reinterpret_cast<const float4*>(W + (size_t)(n0 + w_row) * K + kb + w_col);
            else
                wr = *reinterpret_cast<const float4*>(W + (size_t)(kb + w_kr) * N + n0 + w_nc);
        }
    };
    auto storeT = [&]() {
        As[a_col + 0][a_row] = ar0.x;  As[a_col + 1][a_row] = ar0.y;
        As[a_col + 2][a_row] = ar0.z;  As[a_col + 3][a_row] = ar0.w;
        As[a_col + 0][a_row + 64] = ar1.x;  As[a_col + 1][a_row + 64] = ar1.y;
        As[a_col + 2][a_row + 64] = ar1.z;  As[a_col + 3][a_row + 64] = ar1.w;
        if (MODE == 2) {
            *reinterpret_cast<float4*>(&Ws[w_kr][w_nc]) = wr;
        } else {
            Ws[w_col + 0][w_row] = wr.x;  Ws[w_col + 1][w_row] = wr.y;
            Ws[w_col + 2][w_row] = wr.z;  Ws[w_col + 3][w_row] = wr.w;
        }
    };

    const int nk = K >> 4;
    loadT(0);
    for (int kt = 0; kt < nk; kt++) {
        __syncthreads();
        storeT();
        __syncthreads();
        if (kt + 1 < nk) loadT(kt + 1);
#pragma unroll
        for (int k = 0; k < 16; k++) {
            float4 a0 = *reinterpret_cast<const float4*>(&As[k][cm]);
            float4 a1 = *reinterpret_cast<const float4*>(&As[k][cm + 32]);
            float4 wv = *reinterpret_cast<const float4*>(&Ws[k][cn]);
            float am[8] = {a0.x, a0.y, a0.z, a0.w, a1.x, a1.y, a1.z, a1.w};
            float wl[4] = {wv.x, wv.y, wv.z, wv.w};
#pragma unroll
            for (int i = 0; i < 8; i++)
#pragma unroll
                for (int j = 0; j < 4; j++)
                    acc[i][j] = fmaf(am[i], wl[j], acc[i][j]);
        }
    }

    float bv[4] = {0.f, 0.f, 0.f, 0.f};
    if (HASB) {
#pragma unroll
        for (int j = 0; j < 4; j++) bv[j] = bias[n0 + cn + j];
    }
#pragma unroll
    for (int i = 0; i < 8; i++) {
        int row = m0 + cm + ((i < 4) ? i : (i + 28));
        float4 r;
        float* rr = &r.x;
#pragma unroll
        for (int j = 0; j < 4; j++) {
            float v = acc[i][j] + bv[j];
            if (EPI == 1) {                         // silu
                v = v / (1.f + expf(-v));
            } else if (EPI == 2) {                  // sigmoid + clip
                v = 1.f / (1.f + expf(-v));
                v = fminf(fmaxf(v, 1e-4f), 1.f);
            }
            rr[j] = v;
        }
        *reinterpret_cast<float4*>(out + (size_t)row * N + n0 + cn) = r;
    }
}

// ---------------- small B/C projection GEMM: [4096,2048] x [16,2048]^T (x2) ----------------
__global__ __launch_bounds__(256)
void bc_gemm(const float* __restrict__ u, const float* __restrict__ Bw,
             const float* __restrict__ Cw)
{
    __shared__ float us[32][65];
    __shared__ float ws[32][65];
    const int tid  = threadIdx.x;
    const int row0 = blockIdx.x * 32;
    const int c  = tid & 31;   // 0..15 -> B, 16..31 -> C
    const int rq = tid >> 5;   // 0..7 -> rows rq*4 + i
    float acc[4] = {0.f, 0.f, 0.f, 0.f};

    for (int kt = 0; kt < DINNER; kt += 64) {
        __syncthreads();
#pragma unroll
        for (int s = 0; s < 8; s++) {
            int e = tid + s * 256;
            int r = e >> 6, k = e & 63;
            us[r][k] = u[(size_t)(row0 + r) * DINNER + kt + k];
            ws[r][k] = (r < 16) ? Bw[r * DINNER + kt + k]
                                : Cw[(r - 16) * DINNER + kt + k];
        }
        __syncthreads();
#pragma unroll 8
        for (int k = 0; k < 64; k++) {
            float wv = ws[c][k];
#pragma unroll
            for (int i = 0; i < 4; i++)
                acc[i] = fmaf(us[rq * 4 + i][k], wv, acc[i]);
        }
    }
#pragma unroll
    for (int i = 0; i < 4; i++) {
        int row = row0 + rq * 4 + i;
        if (c < 16) g_Bm[(size_t)row * DSTATE + c]        = acc[i];
        else        g_Cm[(size_t)row * DSTATE + (c - 16)] = acc[i];
    }
}

// ---------------- selective scan: thread per (b, d, n); 16-lane shfl reduce ----------------
__global__ __launch_bounds__(512)
void scan_k(const float* __restrict__ u, const float* __restrict__ dt,
            const float* __restrict__ Bm, const float* __restrict__ Cm,
            const float* __restrict__ Alog, const float* __restrict__ Dp,
            const float* __restrict__ sz, float* __restrict__ y)
{
    const int tid = threadIdx.x;
    const int b   = blockIdx.x >> 6;             // 0..1
    const int d0  = (blockIdx.x & 63) * 32;
    const int dl  = tid >> 4;                    // 0..31
    const int n   = tid & 15;
    const int d   = d0 + dl;
    const float Areg = -expf(Alog[d * DSTATE + n]);
    const float Dreg = Dp[d];
    const size_t rowbase = (size_t)b * SEQLEN;
    float state = 0.f;

    __shared__ float dt_s[2][32][32];
    __shared__ float u_s [2][32][32];
    __shared__ float sz_s[2][32][32];
    __shared__ float B_s [2][32][16];
    __shared__ float C_s [2][32][16];
    __shared__ float y_s [32][32];

    auto stage = [&](int buf, int l0) {
#pragma unroll
        for (int s = 0; s < 2; s++) {
            int e = tid + s * 512;
            int ll = e >> 5, dd = e & 31;
            size_t g = (rowbase + l0 + ll) * DINNER + d0 + dd;
            dt_s[buf][ll][dd] = dt[g];
            u_s [buf][ll][dd] = u[g];
            sz_s[buf][ll][dd] = sz[g];
        }
        {
            int ll = tid >> 4, nn = tid & 15;
            size_t g = (rowbase + l0 + ll) * DSTATE + nn;
            B_s[buf][ll][nn] = Bm[g];
            C_s[buf][ll][nn] = Cm[g];
        }
    };

    stage(0, 0);
    __syncthreads();
    int buf = 0;
    for (int t = 0; t < SEQLEN / 32; t++) {
        const int l0 = t * 32;
        if (t + 1 < SEQLEN / 32) stage(buf ^ 1, l0 + 32);
#pragma unroll 4
        for (int ll = 0; ll < 32; ll++) {
            float dtv = dt_s[buf][ll][dl];
            float uv  = u_s [buf][ll][dl];
            float Bn  = B_s [buf][ll][n];
            float Cn  = C_s [buf][ll][n];
            float arg = fminf(fmaxf(dtv * Areg, -5.f), 5.f);
            float dA  = __expf(arg);
            float dB  = dtv * uv * Bn;
            state = fmaf(dA, state, dB + 1e-6f);
            float v = state * Cn;
            v += __shfl_xor_sync(0xffffffffu, v, 8);
            v += __shfl_xor_sync(0xffffffffu, v, 4);
            v += __shfl_xor_sync(0xffffffffu, v, 2);
            v += __shfl_xor_sync(0xffffffffu, v, 1);
            if (n == 0) y_s[ll][dl] = v + Dreg * uv;
        }
        __syncthreads();
#pragma unroll
        for (int s = 0; s < 2; s++) {
            int e = tid + s * 512;
            int ll = e >> 5, dd = e & 31;
            size_t g = (rowbase + l0 + ll) * DINNER + d0 + dd;
            y[g] = y_s[ll][dd] * sz_s[buf][ll][dd];
        }
        __syncthreads();
        buf ^= 1;
    }
}

// ---------------- launch ----------------
extern "C" void kernel_launch(void* const* d_in, const int* in_sizes, int n_in,
                              void* d_out, int out_size)
{
    (void)in_sizes; (void)n_in; (void)out_size;
    const float* x       = (const float*)d_in[0];
    const float* in_proj = (const float*)d_in[1];
    const float* conv_w  = (const float*)d_in[2];
    const float* conv_b  = (const float*)d_in[3];
    const float* dt_w    = (const float*)d_in[4];
    const float* dt_b    = (const float*)d_in[5];
    const float* A_log   = (const float*)d_in[6];
    const float* Dp      = (const float*)d_in[7];
    const float* B_w     = (const float*)d_in[8];
    const float* C_w     = (const float*)d_in[9];
    const float* out_w   = (const float*)d_in[10];
    float* out = (float*)d_out;

    float *s, *u, *dtp, *y, *P, *Mf, *Bm, *Cm;
    cudaGetSymbolAddress((void**)&s,  g_s);
    cudaGetSymbolAddress((void**)&u,  g_u);
    cudaGetSymbolAddress((void**)&dtp,g_dt);
    cudaGetSymbolAddress((void**)&y,  g_y);
    cudaGetSymbolAddress((void**)&P,  g_P);
    cudaGetSymbolAddress((void**)&Mf, g_M);
    cudaGetSymbolAddress((void**)&Bm, g_Bm);
    cudaGetSymbolAddress((void**)&Cm, g_Cm);

    // 1) repack conv weights per tap
    pack_conv<<<16384, 256>>>(conv_w);

    // 2) fold: M_k = P_k[2048,2048] @ Wxc[2048,1024]   (MODE 2)
    for (int k = 0; k < 4; k++)
        gemm_k<2, 0, false><<<dim3(DMODEL / 64, DINNER / 128), 256>>>(
            P + (size_t)k * DINNER * DINNER, in_proj, nullptr,
            Mf + (size_t)k * DINNER * DMODEL, DINNER, DMODEL, DINNER);

    // 3) silu(z) = silu(x @ Wz^T)   (MODE 0, EPI silu)
    gemm_k<0, 1, false><<<dim3(DINNER / 64, NTOK / 128), 256>>>(
        x, in_proj + (size_t)DINNER * DMODEL, nullptr, s, NTOK, DINNER, DMODEL);

    // 4) u = conv fold: sum_k shift(x, k-3) @ M_k^T + conv_b   (MODE 1)
    gemm_k<1, 0, true><<<dim3(DINNER / 64, NTOK / 128), 256>>>(
        x, Mf, conv_b, u, NTOK, DINNER, 4 * DMODEL);

    // 5) dt = clip(sigmoid(u @ dt_w^T + dt_b), 1e-4, 1)
    gemm_k<0, 2, true><<<dim3(DINNER / 64, NTOK / 128), 256>>>(
        u, dt_w, dt_b, dtp, NTOK, DINNER, DINNER);

    // 6) Bm, Cm projections
    bc_gemm<<<NTOK / 32, 256>>>(u, B_w, C_w);

    // 7) selective scan (writes y * silu(z))
    scan_k<<<128, 512>>>(u, dtp, Bm, Cm, A_log, Dp, s, y);

    // 8) out = y @ out_w^T
    gemm_k<0, 0, false><<<dim3(DMODEL / 64, NTOK / 128), 256>>>(
        y, out_w, nullptr, out, NTOK, DMODEL, DINNER);
}

// round 3
// speedup vs baseline: 1.8453x; 1.8453x over previous
#include <cuda_runtime.h>
#include <cuda_bf16.h>
#include <math.h>
#include <stdint.h>

#define DMODEL 1024
#define DINNER 2048
#define DSTATE 16
#define SEQLEN 2048
#define NTOK   4096   /* BATCH * SEQLEN */

// ---------------- scratch (device globals; no runtime allocation) ----------------
__device__ __nv_bfloat16 g_xh [NTOK * DMODEL],  g_xl [NTOK * DMODEL];
__device__ __nv_bfloat16 g_wzh[DINNER * DMODEL], g_wzl[DINNER * DMODEL];
__device__ __nv_bfloat16 g_wth[DMODEL * DINNER], g_wtl[DMODEL * DINNER]; // WxcT
__device__ __nv_bfloat16 g_Ph [4u * DINNER * DINNER], g_Pl [4u * DINNER * DINNER];
__device__ float         g_Mf [4u * DINNER * DMODEL];
__device__ __nv_bfloat16 g_Mbh[DINNER * 4 * DMODEL], g_Mbl[DINNER * 4 * DMODEL];
__device__ __nv_bfloat16 g_dwh[DINNER * DINNER], g_dwl[DINNER * DINNER];
__device__ __nv_bfloat16 g_owh[DMODEL * DINNER], g_owl[DMODEL * DINNER];
__device__ float         g_u  [NTOK * DINNER];
__device__ __nv_bfloat16 g_uh [NTOK * DINNER], g_ul [NTOK * DINNER];
__device__ float         g_s  [NTOK * DINNER];       // silu(z)
__device__ float         g_dt [NTOK * DINNER];
__device__ __nv_bfloat16 g_yh [NTOK * DINNER], g_yl [NTOK * DINNER];
__device__ float         g_Bm [NTOK * DSTATE], g_Cm [NTOK * DSTATE];

// ---------------- helpers ----------------
__device__ __forceinline__ uint32_t smem_u32(const void* p) {
    uint32_t a;
    asm("{ .reg .u64 t; cvta.to.shared.u64 t, %1; cvt.u32.u64 %0, t; }" : "=r"(a) : "l"(p));
    return a;
}
__device__ __forceinline__ void split2(float v, __nv_bfloat16& h, __nv_bfloat16& l) {
    h = __float2bfloat16(v);
    l = __float2bfloat16(v - __bfloat162float(h));
}

#define LDSM4(r, a) asm volatile( \
    "ldmatrix.sync.aligned.m8n8.x4.shared.b16 {%0,%1,%2,%3}, [%4];" \
    : "=r"((r)[0]), "=r"((r)[1]), "=r"((r)[2]), "=r"((r)[3]) : "r"(a))

#define MMA16816(c, a, b0, b1) asm volatile( \
    "mma.sync.aligned.m16n8k16.row.col.f32.bf16.bf16.f32 " \
    "{%0,%1,%2,%3},{%4,%5,%6,%7},{%8,%9},{%0,%1,%2,%3};" \
    : "+f"((c)[0]), "+f"((c)[1]), "+f"((c)[2]), "+f"((c)[3]) \
    : "r"((a)[0]), "r"((a)[1]), "r"((a)[2]), "r"((a)[3]), "r"(b0), "r"(b1))

#define CPA(dst, src, sz) asm volatile( \
    "cp.async.cg.shared.global [%0], [%1], 16, %2;" :: "r"(dst), "l"(src), "r"(sz))

// ---------------- conversion kernels ----------------
__global__ void split_k(const float* __restrict__ in, __nv_bfloat16* __restrict__ h,
                        __nv_bfloat16* __restrict__ l) {
    int i = blockIdx.x * 256 + threadIdx.x;
    float4 v = reinterpret_cast<const float4*>(in)[i];
    float vv[4] = {v.x, v.y, v.z, v.w};
    __nv_bfloat16 hh[4], ll[4];
#pragma unroll
    for (int j = 0; j < 4; j++) split2(vv[j], hh[j], ll[j]);
    reinterpret_cast<__nv_bfloat162*>(h)[2 * i]     = __nv_bfloat162(hh[0], hh[1]);
    reinterpret_cast<__nv_bfloat162*>(h)[2 * i + 1] = __nv_bfloat162(hh[2], hh[3]);
    reinterpret_cast<__nv_bfloat162*>(l)[2 * i]     = __nv_bfloat162(ll[0], ll[1]);
    reinterpret_cast<__nv_bfloat162*>(l)[2 * i + 1] = __nv_bfloat162(ll[2], ll[3]);
}

// transpose-split: in_proj rows 0..2047 ([2048,1024]) -> WxcT [1024,2048]
__global__ void tsplit_k(const float* __restrict__ w, __nv_bfloat16* __restrict__ th,
                         __nv_bfloat16* __restrict__ tl) {
    __shared__ float t[32][33];
    int j0 = blockIdx.x * 32, i0 = blockIdx.y * 32;
    int tx = threadIdx.x & 31, ty4 = threadIdx.x >> 5;
#pragma unroll
    for (int s = 0; s < 4; s++) {
        int ty = ty4 + s * 8;
        t[ty][tx] = w[(size_t)(i0 + ty) * DMODEL + j0 + tx];
    }
    __syncthreads();
#pragma unroll
    for (int s = 0; s < 4; s++) {
        int ty = ty4 + s * 8;
        __nv_bfloat16 h, l;
        split2(t[tx][ty], h, l);
        th[(size_t)(j0 + ty) * DINNER + i0 + tx] = h;
        tl[(size_t)(j0 + ty) * DINNER + i0 + tx] = l;
    }
}

// Mf [(tap*2048+d), j] fp32 -> Mb[d][tap*1024+j] bf16 hi/lo
__global__ void mrelayout_k(const float* __restrict__ mf) {
    int g = blockIdx.x * 256 + threadIdx.x;
    int e = g * 4, row = e >> 10, j = e & 1023;
    int tap = row >> 11, d = row & 2047;
    float4 v = reinterpret_cast<const float4*>(mf)[g];
    float vv[4] = {v.x, v.y, v.z, v.w};
    size_t dst = (size_t)d * 4096 + tap * 1024 + j;
    __nv_bfloat16 hh[4], ll[4];
#pragma unroll
    for (int q = 0; q < 4; q++) split2(vv[q], hh[q], ll[q]);
    *reinterpret_cast<__nv_bfloat162*>(g_Mbh + dst)     = __nv_bfloat162(hh[0], hh[1]);
    *reinterpret_cast<__nv_bfloat162*>(g_Mbh + dst + 2) = __nv_bfloat162(hh[2], hh[3]);
    *reinterpret_cast<__nv_bfloat162*>(g_Mbl + dst)     = __nv_bfloat162(ll[0], ll[1]);
    *reinterpret_cast<__nv_bfloat162*>(g_Mbl + dst + 2) = __nv_bfloat162(ll[2], ll[3]);
}

// conv_w [d][i][4] -> P_hi/lo [tap][d][i]
__global__ void pack_split_k(const float* __restrict__ cw) {
    int g = blockIdx.x * 256 + threadIdx.x;
    float4 v = reinterpret_cast<const float4*>(cw)[g];
    float vv[4] = {v.x, v.y, v.z, v.w};
#pragma unroll
    for (int t = 0; t < 4; t++) {
        __nv_bfloat16 h, l;
        split2(vv[t], h, l);
        g_Ph[(size_t)t * 4194304u + g] = h;
        g_Pl[(size_t)t * 4194304u + g] = l;
    }
}

// ---------------- HMMA bf16x3 GEMM: D = A @ B^T (both operands K-major) ----------------
// MODE 0: normal. MODE 1: conv-fold (A = x with per-1024-K-chunk row shift tap-3).
// EPI 0: none, 1: silu, 2: sigmoid+clip. HASB: +bias[n]. HILO: also write bf16 hi/lo split.
#define PITCH_B 80                 // bytes per smem row (40 halves) -> conflict-free ldmatrix
#define MATB    (128 * PITCH_B)    // 10240 B per matrix tile
#define STAGEB  (4 * MATB)         // Ah, Al, Bh, Bl
#define GSMEM   (2 * STAGEB)       // 81920

template<int MODE, int EPI, bool HASB, bool HILO>
__global__ __launch_bounds__(256)
void tgemm(const __nv_bfloat16* __restrict__ Ah, const __nv_bfloat16* __restrict__ Al,
           const __nv_bfloat16* __restrict__ Bh, const __nv_bfloat16* __restrict__ Bl,
           const float* __restrict__ bias, float* __restrict__ out,
           __nv_bfloat16* __restrict__ oh, __nv_bfloat16* __restrict__ ol,
           int M, int N, int K)
{
    extern __shared__ char sm_[];
    const int tid = threadIdx.x, lane = tid & 31, wid = tid >> 5;
    const int m0 = blockIdx.y * 128, n0 = blockIdx.x * 128;
    const uint32_t sb = smem_u32(sm_);

    const int wm = wid >> 2, wn = wid & 3;          // warp tile: 64(m) x 32(n)
    const int lr = lane & 15, lc8 = (lane >> 4) * 8;
    const uint32_t aoffH = (uint32_t)((wm * 64 + lr) * PITCH_B + lc8 * 2);
    const uint32_t aoffL = aoffH + MATB;
    const uint32_t boffH = (uint32_t)(2 * MATB + (wn * 32 + lr) * PITCH_B + lc8 * 2);
    const uint32_t boffL = boffH + MATB;

    float acc[4][4][4] = {};

    auto ldst = [&](int kt) {
        const uint32_t st = sb + (kt & 1) * STAGEB;
        const int kb = kt * 32;
#pragma unroll
        for (int q = 0; q < 8; q++) {
            int cid = q * 256 + tid;
            int mat = cid >> 9, w = cid & 511, row = w >> 2, c = w & 3;
            uint32_t dst = st + mat * MATB + row * PITCH_B + c * 16;
            const __nv_bfloat16* src;
            uint32_t sz = 16;
            if (mat < 2) {
                const __nv_bfloat16* base = mat ? Al : Ah;
                if (MODE == 1) {
                    int tap = kb >> 10, jb = kb & 1023, rg = m0 + row;
                    if (((rg & (SEQLEN - 1)) + tap - 3) < 0) { sz = 0; src = base; }
                    else src = base + (size_t)(rg + tap - 3) * DMODEL + jb + c * 8;
                } else {
                    src = base + (size_t)(m0 + row) * K + kb + c * 8;
                }
            } else {
                src = ((mat == 3) ? Bl : Bh) + (size_t)(n0 + row) * K + kb + c * 8;
            }
            CPA(dst, src, sz);
        }
        asm volatile("cp.async.commit_group;" ::: "memory");
    };

    auto comp = [&](int s) {
        const uint32_t st = sb + s * STAGEB;
#pragma unroll
        for (int kk = 0; kk < 2; kk++) {
            const uint32_t ko = kk * 32;            // 16 halves = 32 bytes
            uint32_t ah[4][4], bhf[2][4], blf[2][4];
#pragma unroll
            for (int mt = 0; mt < 4; mt++) LDSM4(ah[mt], st + aoffH + mt * 16 * PITCH_B + ko);
#pragma unroll
            for (int np = 0; np < 2; np++) LDSM4(bhf[np], st + boffH + np * 16 * PITCH_B + ko);
#pragma unroll
            for (int mt = 0; mt < 4; mt++)
#pragma unroll
                for (int nt = 0; nt < 4; nt++)
                    MMA16816(acc[mt][nt], ah[mt], bhf[nt >> 1][nt & 1], bhf[nt >> 1][2 + (nt & 1)]);
#pragma unroll
            for (int np = 0; np < 2; np++) LDSM4(blf[np], st + boffL + np * 16 * PITCH_B + ko);
#pragma unroll
            for (int mt = 0; mt < 4; mt++)
#pragma unroll
                for (int nt = 0; nt < 4; nt++)
                    MMA16816(acc[mt][nt], ah[mt], blf[nt >> 1][nt & 1], blf[nt >> 1][2 + (nt & 1)]);
#pragma unroll
            for (int mt = 0; mt < 4; mt++) {
                uint32_t alf[4];
                LDSM4(alf, st + aoffL + mt * 16 * PITCH_B + ko);
#pragma unroll
                for (int nt = 0; nt < 4; nt++)
                    MMA16816(acc[mt][nt], alf, bhf[nt >> 1][nt & 1], bhf[nt >> 1][2 + (nt & 1)]);
            }
        }
    };

    const int nk = K >> 5;
    ldst(0);
    for (int kt = 0; kt < nk; kt++) {
        if (kt + 1 < nk) { ldst(kt + 1); asm volatile("cp.async.wait_group 1;" ::: "memory"); }
        else             { asm volatile("cp.async.wait_group 0;" ::: "memory"); }
        __syncthreads();
        comp(kt & 1);
        __syncthreads();
    }

    // epilogue from register accumulators
    const int g = lane >> 2, tg = lane & 3;
#pragma unroll
    for (int mt = 0; mt < 4; mt++) {
#pragma unroll
        for (int nt = 0; nt < 4; nt++) {
            const int col = n0 + wn * 32 + nt * 8 + tg * 2;
            float b0 = 0.f, b1 = 0.f;
            if (HASB) { b0 = bias[col]; b1 = bias[col + 1]; }
#pragma unroll
            for (int h = 0; h < 2; h++) {
                const int r = m0 + wm * 64 + mt * 16 + g + h * 8;
                float v0 = acc[mt][nt][2 * h + 0] + b0;
                float v1 = acc[mt][nt][2 * h + 1] + b1;
                if (EPI == 1) {
                    v0 = v0 / (1.f + __expf(-v0));
                    v1 = v1 / (1.f + __expf(-v1));
                } else if (EPI == 2) {
                    v0 = fminf(fmaxf(1.f / (1.f + __expf(-v0)), 1e-4f), 1.f);
                    v1 = fminf(fmaxf(1.f / (1.f + __expf(-v1)), 1e-4f), 1.f);
                }
                *reinterpret_cast<float2*>(out + (size_t)r * N + col) = make_float2(v0, v1);
                if (HILO) {
                    __nv_bfloat16 h0, l0, h1, l1;
                    split2(v0, h0, l0); split2(v1, h1, l1);
                    *reinterpret_cast<__nv_bfloat162*>(oh + (size_t)r * N + col) = __nv_bfloat162(h0, h1);
                    *reinterpret_cast<__nv_bfloat162*>(ol + (size_t)r * N + col) = __nv_bfloat162(l0, l1);
                }
            }
        }
    }
}

// ---------------- small B/C projection GEMM ----------------
__global__ __launch_bounds__(256)
void bc_gemm(const float* __restrict__ u, const float* __restrict__ Bw,
             const float* __restrict__ Cw)
{
    __shared__ float us[32][65];
    __shared__ float ws[32][65];
    const int tid  = threadIdx.x;
    const int row0 = blockIdx.x * 32;
    const int c  = tid & 31;
    const int rq = tid >> 5;
    float acc[4] = {0.f, 0.f, 0.f, 0.f};

    for (int kt = 0; kt < DINNER; kt += 64) {
        __syncthreads();
#pragma unroll
        for (int s = 0; s < 8; s++) {
            int e = tid + s * 256;
            int r = e >> 6, k = e & 63;
            us[r][k] = u[(size_t)(row0 + r) * DINNER + kt + k];
            ws[r][k] = (r < 16) ? Bw[r * DINNER + kt + k]
                                : Cw[(r - 16) * DINNER + kt + k];
        }
        __syncthreads();
#pragma unroll 8
        for (int k = 0; k < 64; k++) {
            float wv = ws[c][k];
#pragma unroll
            for (int i = 0; i < 4; i++)
                acc[i] = fmaf(us[rq * 4 + i][k], wv, acc[i]);
        }
    }
#pragma unroll
    for (int i = 0; i < 4; i++) {
        int row = row0 + rq * 4 + i;
        if (c < 16) g_Bm[(size_t)row * DSTATE + c]        = acc[i];
        else        g_Cm[(size_t)row * DSTATE + (c - 16)] = acc[i];
    }
}

// ---------------- selective scan (emits pre-split y for the out GEMM) ----------------
__global__ __launch_bounds__(512)
void scan_k(const float* __restrict__ u, const float* __restrict__ dt,
            const float* __restrict__ Bm, const float* __restrict__ Cm,
            const float* __restrict__ Alog, const float* __restrict__ Dp,
            const float* __restrict__ sz,
            __nv_bfloat16* __restrict__ yh, __nv_bfloat16* __restrict__ yl)
{
    const int tid = threadIdx.x;
    const int b   = blockIdx.x >> 6;
    const int d0  = (blockIdx.x & 63) * 32;
    const int dl  = tid >> 4;
    const int n   = tid & 15;
    const int d   = d0 + dl;
    const float Areg = -expf(Alog[d * DSTATE + n]);
    const float Dreg = Dp[d];
    const size_t rowbase = (size_t)b * SEQLEN;
    float state = 0.f;

    __shared__ float dt_s[2][32][32];
    __shared__ float u_s [2][32][32];
    __shared__ float sz_s[2][32][32];
    __shared__ float B_s [2][32][16];
    __shared__ float C_s [2][32][16];
    __shared__ float y_s [32][32];

    auto stage = [&](int buf, int l0) {
#pragma unroll
        for (int s = 0; s < 2; s++) {
            int e = tid + s * 512;
            int ll = e >> 5, dd = e & 31;
            size_t g = (rowbase + l0 + ll) * DINNER + d0 + dd;
            dt_s[buf][ll][dd] = dt[g];
            u_s [buf][ll][dd] = u[g];
            sz_s[buf][ll][dd] = sz[g];
        }
        {
            int ll = tid >> 4, nn = tid & 15;
            size_t g = (rowbase + l0 + ll) * DSTATE + nn;
            B_s[buf][ll][nn] = Bm[g];
            C_s[buf][ll][nn] = Cm[g];
        }
    };

    stage(0, 0);
    __syncthreads();
    int buf = 0;
    for (int t = 0; t < SEQLEN / 32; t++) {
        const int l0 = t * 32;
        if (t + 1 < SEQLEN / 32) stage(buf ^ 1, l0 + 32);
#pragma unroll 4
        for (int ll = 0; ll < 32; ll++) {
            float dtv = dt_s[buf][ll][dl];
            float uv  = u_s [buf][ll][dl];
            float Bn  = B_s [buf][ll][n];
            float Cn  = C_s [buf][ll][n];
            float arg = fminf(fmaxf(dtv * Areg, -5.f), 5.f);
            float dA  = __expf(arg);
            float dB  = dtv * uv * Bn;
            state = fmaf(dA, state, dB + 1e-6f);
            float v = state * Cn;
            v += __shfl_xor_sync(0xffffffffu, v, 8);
            v += __shfl_xor_sync(0xffffffffu, v, 4);
            v += __shfl_xor_sync(0xffffffffu, v, 2);
            v += __shfl_xor_sync(0xffffffffu, v, 1);
            if (n == 0) y_s[ll][dl] = v + Dreg * uv;
        }
        __syncthreads();
#pragma unroll
        for (int s = 0; s < 2; s++) {
            int e = tid + s * 512;
            int ll = e >> 5, dd = e & 31;
            size_t g = (rowbase + l0 + ll) * DINNER + d0 + dd;
            float v = y_s[ll][dd] * sz_s[buf][ll][dd];
            __nv_bfloat16 h, l;
            split2(v, h, l);
            yh[g] = h; yl[g] = l;
        }
        __syncthreads();
        buf ^= 1;
    }
}

// ---------------- launch ----------------
extern "C" void kernel_launch(void* const* d_in, const int* in_sizes, int n_in,
                              void* d_out, int out_size)
{
    (void)in_sizes; (void)n_in; (void)out_size;
    const float* x       = (const float*)d_in[0];
    const float* in_proj = (const float*)d_in[1];
    const float* conv_w  = (const float*)d_in[2];
    const float* conv_b  = (const float*)d_in[3];
    const float* dt_w    = (const float*)d_in[4];
    const float* dt_b    = (const float*)d_in[5];
    const float* A_log   = (const float*)d_in[6];
    const float* Dp      = (const float*)d_in[7];
    const float* B_w     = (const float*)d_in[8];
    const float* C_w     = (const float*)d_in[9];
    const float* out_w   = (const float*)d_in[10];
    float* out = (float*)d_out;

    auto ga = [](const void* sym) { void* p; cudaGetSymbolAddress(&p, sym); return p; };
    __nv_bfloat16* xh  = (__nv_bfloat16*)ga(g_xh);   __nv_bfloat16* xl  = (__nv_bfloat16*)ga(g_xl);
    __nv_bfloat16* wzh = (__nv_bfloat16*)ga(g_wzh);  __nv_bfloat16* wzl = (__nv_bfloat16*)ga(g_wzl);
    __nv_bfloat16* wth = (__nv_bfloat16*)ga(g_wth);  __nv_bfloat16* wtl = (__nv_bfloat16*)ga(g_wtl);
    __nv_bfloat16* Ph  = (__nv_bfloat16*)ga(g_Ph);   __nv_bfloat16* Pl  = (__nv_bfloat16*)ga(g_Pl);
    float*         Mf  = (float*)ga(g_Mf);
    __nv_bfloat16* Mbh = (__nv_bfloat16*)ga(g_Mbh);  __nv_bfloat16* Mbl = (__nv_bfloat16*)ga(g_Mbl);
    __nv_bfloat16* dwh = (__nv_bfloat16*)ga(g_dwh);  __nv_bfloat16* dwl = (__nv_bfloat16*)ga(g_dwl);
    __nv_bfloat16* owh = (__nv_bfloat16*)ga(g_owh);  __nv_bfloat16* owl = (__nv_bfloat16*)ga(g_owl);
    float* u  = (float*)ga(g_u);
    __nv_bfloat16* uh = (__nv_bfloat16*)ga(g_uh);    __nv_bfloat16* ul = (__nv_bfloat16*)ga(g_ul);
    float* s  = (float*)ga(g_s);
    float* dtp = (float*)ga(g_dt);
    __nv_bfloat16* yh = (__nv_bfloat16*)ga(g_yh);    __nv_bfloat16* yl = (__nv_bfloat16*)ga(g_yl);
    float* Bm = (float*)ga(g_Bm);
    float* Cm = (float*)ga(g_Cm);

    cudaFuncSetAttribute(tgemm<0,0,false,false>, cudaFuncAttributeMaxDynamicSharedMemorySize, GSMEM);
    cudaFuncSetAttribute(tgemm<0,1,false,false>, cudaFuncAttributeMaxDynamicSharedMemorySize, GSMEM);
    cudaFuncSetAttribute(tgemm<1,0,true,true>,   cudaFuncAttributeMaxDynamicSharedMemorySize, GSMEM);
    cudaFuncSetAttribute(tgemm<0,2,true,false>,  cudaFuncAttributeMaxDynamicSharedMemorySize, GSMEM);

    // conversions
    split_k<<<4096, 256>>>(x, xh, xl);                                   // x
    split_k<<<2048, 256>>>(in_proj + (size_t)DINNER * DMODEL, wzh, wzl); // Wz
    tsplit_k<<<dim3(32, 64), 256>>>(in_proj, wth, wtl);                  // WxcT
    split_k<<<4096, 256>>>(dt_w, dwh, dwl);                              // dt_w
    split_k<<<2048, 256>>>(out_w, owh, owl);                             // out_w
    pack_split_k<<<16384, 256>>>(conv_w);                                // conv taps

    // fold: M_k = P_k @ Wxc   (M=8192, N=1024, K=2048)
    tgemm<0,0,false,false><<<dim3(8, 64), 256, GSMEM>>>(
        Ph, Pl, wth, wtl, nullptr, Mf, nullptr, nullptr, 8192, 1024, 2048);
    mrelayout_k<<<8192, 256>>>(Mf);

    // silu(z) = silu(x @ Wz^T)
    tgemm<0,1,false,false><<<dim3(16, 32), 256, GSMEM>>>(
        xh, xl, wzh, wzl, nullptr, s, nullptr, nullptr, NTOK, DINNER, DMODEL);

    // u = conv fold (shifted K=4096) + conv_b, also emits hi/lo split
    tgemm<1,0,true,true><<<dim3(16, 32), 256, GSMEM>>>(
        xh, xl, Mbh, Mbl, conv_b, u, uh, ul, NTOK, DINNER, 4 * DMODEL);

    // dt = clip(sigmoid(u @ dt_w^T + dt_b))
    tgemm<0,2,true,false><<<dim3(16, 32), 256, GSMEM>>>(
        uh, ul, dwh, dwl, dt_b, dtp, nullptr, nullptr, NTOK, DINNER, DINNER);

    // B/C projections
    bc_gemm<<<NTOK / 32, 256>>>(u, B_w, C_w);

    // selective scan -> y (pre-split bf16 hi/lo)
    scan_k<<<128, 512>>>(u, dtp, Bm, Cm, A_log, Dp, s, yh, yl);

    // out = y @ out_w^T
    tgemm<0,0,false,false><<<dim3(8, 32), 256, GSMEM>>>(
        yh, yl, owh, owl, nullptr, out, nullptr, nullptr, NTOK, DMODEL, DINNER);
}